// round 5
// baseline (speedup 1.0000x reference)
#include <cuda_runtime.h>
#include <math.h>

#define EPSV 1e-5f
#define HW   65536
#define CCH  64
#define NB   8
#define TP   128

// ---------------- scratch (device globals; no runtime allocation) ----------
__device__ float    g_sumx[2*NB*CCH];
__device__ unsigned g_cmax[2*NB*CCH];
__device__ unsigned g_kmax[2*NB];
__device__ float    g_klog[2*NB*HW];     // 4 MB
__device__ float    g_fea [2*NB*CCH];
__device__ float    g_Z   [2*NB];
__device__ float    g_avg [2*NB*CCH];
__device__ float    g_msm [2*NB*CCH];
__device__ float    g_gate[2*NB*CCH];
__device__ float    g_half[2*NB*HW];     // 4 MB
__device__ float    g_keywf[CCH];
__device__ float    g_valwf[CCH*CCH];
__device__ float    g_valoff[CCH];
__device__ float    g_sc[4];             // keyoff, hw0, hw1, hoff

typedef unsigned long long ull;

// ---- f32x2 packed math (FFMA2 — only reachable via PTX) -------------------
__device__ __forceinline__ ull pack2(float a, float b) {
    ull r; asm("mov.b64 %0, {%1, %2};" : "=l"(r) : "f"(a), "f"(b)); return r;
}
__device__ __forceinline__ ull fma2(ull a, ull b, ull c) {
    ull d; asm("fma.rn.f32x2 %0, %1, %2, %3;" : "=l"(d) : "l"(a), "l"(b), "l"(c)); return d;
}
__device__ __forceinline__ float2 unpack2(ull v) {
    float2 f; asm("mov.b64 {%0, %1}, %2;" : "=f"(f.x), "=f"(f.y) : "l"(v)); return f;
}

// ordered-int encoding for float atomicMax
__device__ __forceinline__ unsigned ordf(float f) {
    unsigned u = __float_as_uint(f);
    return (u & 0x80000000u) ? ~u : (u | 0x80000000u);
}
__device__ __forceinline__ float deord(unsigned u) {
    u = (u & 0x80000000u) ? (u & 0x7fffffffu) : ~u;
    return __uint_as_float(u);
}
__device__ __forceinline__ float siluf(float z) {
    return __fdividef(z, 1.f + __expf(-z));
}

// ---------------- init: zero accumulators + fold BN into weights ----------
__global__ void k_init(const float* key_w, const float* key_g, const float* key_b,
                       const float* key_m, const float* key_v,
                       const float* val_w, const float* val_g, const float* val_b,
                       const float* val_m, const float* val_v,
                       const float* half_w, const float* half_g, const float* half_b,
                       const float* half_m, const float* half_v) {
    int t = threadIdx.x;
    for (int i = t; i < 2*NB*CCH; i += blockDim.x) { g_sumx[i] = 0.f; g_cmax[i] = 0u; g_fea[i] = 0.f; }
    for (int i = t; i < 2*NB; i += blockDim.x) { g_kmax[i] = 0u; g_Z[i] = 0.f; }
    if (t < CCH) {
        float ks = key_g[0] * rsqrtf(key_v[0] + EPSV);
        g_keywf[t] = key_w[t] * ks;
        float vs = val_g[t] * rsqrtf(val_v[t] + EPSV);
        g_valoff[t] = val_b[t] - val_m[t] * vs;
        for (int c = 0; c < CCH; c++) g_valwf[t*CCH + c] = val_w[t*CCH + c] * vs;
        if (t == 0) g_sc[0] = key_b[0] - key_m[0] * ks;
        if (t == 1) {
            float hs = half_g[0] * rsqrtf(half_v[0] + EPSV);
            g_sc[1] = half_w[0] * hs;
            g_sc[2] = half_w[1] * hs;
            g_sc[3] = half_b[0] - half_m[0] * hs;
        }
    }
}

// ---------------- pass1: conv_w GEMM -> channel max; x sums; key logits ----
// 256 threads, 64x128 tile. Thread (og=t>>4, pg=t&15) owns channels {og+16i}
// and pixel pairs {2pg+32jp, 2pg+32jp+1}.
__global__ void __launch_bounds__(256, 4)
k_pass1(const float* __restrict__ xr, const float* __restrict__ xi,
        const float* __restrict__ conv_w) {
    extern __shared__ float sm[];
    float* Xs  = sm;             // 64*128
    float* Ws  = sm + 8192;      // 64*65 (padded)
    float* kw  = Ws + 4160;      // 64
    float* red = kw + 64;        // 8
    int s = blockIdx.z, n = blockIdx.y;
    int p0 = blockIdx.x * TP;
    const float* x = (s == 0 ? xr : xi) + (size_t)n * CCH * HW + p0;
    int t = threadIdx.x;

    for (int i4 = t; i4 < 2048; i4 += 256) {
        int c = i4 >> 5, pq = i4 & 31;
        *(float4*)(Xs + c*TP + pq*4) = *(const float4*)(x + (size_t)c*HW + pq*4);
    }
    for (int i = t; i < 4096; i += 256) Ws[(i >> 6)*65 + (i & 63)] = conv_w[i];
    if (t < 64) kw[t] = g_keywf[t];
    __syncthreads();

    int og = t >> 4, pg = t & 15;
    const float* Wb = Ws + og*65;
    const float* Xb = Xs + 2*pg;

    ull acc2[4][4];
    #pragma unroll
    for (int i = 0; i < 4; i++)
        #pragma unroll
        for (int j = 0; j < 4; j++) acc2[i][j] = 0ULL;

    #pragma unroll 2
    for (int c = 0; c < 64; c++) {
        ull wv2[4], xv2[4];
        #pragma unroll
        for (int i = 0; i < 4; i++) { float w = Wb[i*(16*65) + c]; wv2[i] = pack2(w, w); }
        #pragma unroll
        for (int jp = 0; jp < 4; jp++) xv2[jp] = *(const ull*)(Xb + c*TP + 32*jp);
        #pragma unroll
        for (int i = 0; i < 4; i++)
            #pragma unroll
            for (int jp = 0; jp < 4; jp++) acc2[i][jp] = fma2(wv2[i], xv2[jp], acc2[i][jp]);
    }

    int base = (s*NB + n) * CCH;
    // per-channel max over pixels (bias added later)
    #pragma unroll
    for (int i = 0; i < 4; i++) {
        float m = -1e30f;
        #pragma unroll
        for (int jp = 0; jp < 4; jp++) {
            float2 f = unpack2(acc2[i][jp]);
            m = fmaxf(m, fmaxf(f.x, f.y));
        }
        #pragma unroll
        for (int k = 8; k >= 1; k >>= 1) m = fmaxf(m, __shfl_xor_sync(0xffffffffu, m, k));
        if (pg == 0) atomicMax(&g_cmax[base + og + 16*i], ordf(m));
    }
    // per-channel sums of x (exact mean path)
    #pragma unroll
    for (int i = 0; i < 4; i++) {
        int c = og + 16*i;
        float ssum = 0.f;
        #pragma unroll
        for (int jp = 0; jp < 4; jp++) {
            float2 v = *(const float2*)(Xs + c*TP + 2*pg + 32*jp);
            ssum += v.x + v.y;
        }
        #pragma unroll
        for (int k = 8; k >= 1; k >>= 1) ssum += __shfl_xor_sync(0xffffffffu, ssum, k);
        if (pg == 0) atomicAdd(&g_sumx[base + c], ssum);
    }
    // key logit: two threads per pixel, split channel halves
    int p = t >> 1, h = t & 1;
    float z = 0.f;
    #pragma unroll 8
    for (int c = 32*h; c < 32*h + 32; c++) z = fmaf(kw[c], Xs[c*TP + p], z);
    z += __shfl_xor_sync(0xffffffffu, z, 1);
    z += g_sc[0];
    float kl = siluf(z);
    if (h == 0) g_klog[(size_t)(s*NB + n) * HW + p0 + p] = kl;
    float km = (h == 0) ? kl : -1e30f;
    #pragma unroll
    for (int k = 16; k >= 1; k >>= 1) km = fmaxf(km, __shfl_xor_sync(0xffffffffu, km, k));
    if ((t & 31) == 0) red[t >> 5] = km;
    __syncthreads();
    if (t == 0) {
        float m = red[0];
        #pragma unroll
        for (int w = 1; w < 8; w++) m = fmaxf(m, red[w]);
        atomicMax(&g_kmax[s*NB + n], ordf(m));
    }
}

// ---------------- mid: channel softmaxes (avg from sums, max from cmax) ----
__device__ __forceinline__ float blockmax64(float v, float* tmp) {
    tmp[threadIdx.x] = v; __syncthreads();
    for (int k = 32; k >= 1; k >>= 1) {
        if (threadIdx.x < k) tmp[threadIdx.x] = fmaxf(tmp[threadIdx.x], tmp[threadIdx.x + k]);
        __syncthreads();
    }
    float r = tmp[0]; __syncthreads(); return r;
}
__device__ __forceinline__ float blocksum64(float v, float* tmp) {
    tmp[threadIdx.x] = v; __syncthreads();
    for (int k = 32; k >= 1; k >>= 1) {
        if (threadIdx.x < k) tmp[threadIdx.x] += tmp[threadIdx.x + k];
        __syncthreads();
    }
    float r = tmp[0]; __syncthreads(); return r;
}

__global__ void k_mid(const float* __restrict__ conv_w, const float* __restrict__ conv_b) {
    int s = blockIdx.x, n = blockIdx.y, o = threadIdx.x;
    __shared__ float sx[64], tmp[64];
    int base = (s*NB + n) * CCH;
    sx[o] = g_sumx[base + o] * (1.f / (float)HW);
    __syncthreads();
    float mean = conv_b[o];
    for (int c = 0; c < 64; c++) mean = fmaf(sx[c], conv_w[o*64 + c], mean);
    float mx = deord(g_cmax[base + o]) + conv_b[o];

    float m1 = blockmax64(mean, tmp);
    float e1 = expf(mean - m1);
    float s1 = blocksum64(e1, tmp);
    g_avg[base + o] = e1 / s1;

    float m2 = blockmax64(mx, tmp);
    float e2 = expf(mx - m2);
    float s2 = blocksum64(e2, tmp);
    g_msm[base + o] = e2 / s2;
}

// ---------------- pass2: val GEMM + fused fea/Z/half -----------------------
__global__ void __launch_bounds__(256, 4)
k_pass2(const float* __restrict__ xr, const float* __restrict__ xi) {
    extern __shared__ float sm[];
    float* Xs   = sm;            // 8192, reused as V after GEMM
    float* Ws   = sm + 8192;     // 4160
    float* voff = Ws + 4160;     // 64
    float* av   = voff + 64;     // 64
    float* mv   = av + 64;       // 64
    float* es   = mv + 64;       // 128
    float* red  = es + 128;      // 8
    int sx = blockIdx.z, n = blockIdx.y, so = 1 - sx;   // V of side sx feeds output side so
    int p0 = blockIdx.x * TP;
    int t = threadIdx.x;
    const float* x = (sx == 0 ? xr : xi) + (size_t)n * CCH * HW + p0;

    for (int i4 = t; i4 < 2048; i4 += 256) {
        int c = i4 >> 5, pq = i4 & 31;
        *(float4*)(Xs + c*TP + pq*4) = *(const float4*)(x + (size_t)c*HW + pq*4);
    }
    for (int i = t; i < 4096; i += 256) Ws[(i >> 6)*65 + (i & 63)] = g_valwf[i];
    if (t < 64) {
        voff[t] = g_valoff[t];
        int b2 = (so*NB + n) * CCH;
        av[t] = g_avg[b2 + t];
        mv[t] = g_msm[b2 + t];
    }
    __syncthreads();

    int og = t >> 4, pg = t & 15;
    const float* Wb = Ws + og*65;
    const float* Xb = Xs + 2*pg;

    ull acc2[4][4];
    #pragma unroll
    for (int i = 0; i < 4; i++)
        #pragma unroll
        for (int j = 0; j < 4; j++) acc2[i][j] = 0ULL;

    #pragma unroll 2
    for (int c = 0; c < 64; c++) {
        ull wv2[4], xv2[4];
        #pragma unroll
        for (int i = 0; i < 4; i++) { float w = Wb[i*(16*65) + c]; wv2[i] = pack2(w, w); }
        #pragma unroll
        for (int jp = 0; jp < 4; jp++) xv2[jp] = *(const ull*)(Xb + c*TP + 32*jp);
        #pragma unroll
        for (int i = 0; i < 4; i++)
            #pragma unroll
            for (int jp = 0; jp < 4; jp++) acc2[i][jp] = fma2(wv2[i], xv2[jp], acc2[i][jp]);
    }
    __syncthreads();   // done reading Xs; overwrite with V

    #pragma unroll
    for (int i = 0; i < 4; i++) {
        int c = og + 16*i;
        float off = voff[c];
        #pragma unroll
        for (int jp = 0; jp < 4; jp++) {
            float2 f = unpack2(acc2[i][jp]);
            f.x = siluf(f.x + off);
            f.y = siluf(f.y + off);
            *(float2*)(Xs + c*TP + 2*pg + 32*jp) = f;
        }
    }
    __syncthreads();

    // per-pixel: key weight e, half output (two threads per pixel)
    int p = t >> 1, h = t & 1;
    float kmaxv = deord(g_kmax[so*NB + n]);
    float kl = g_klog[(size_t)(so*NB + n) * HW + p0 + p];
    float e = __expf(kl - kmaxv);
    if (h == 0) es[p] = e;
    float sa = 0.f, smx = 0.f;
    #pragma unroll 8
    for (int c = 32*h; c < 32*h + 32; c++) {
        float vv = Xs[c*TP + p];
        sa  = fmaf(av[c], vv, sa);
        smx = fmaf(mv[c], vv, smx);
    }
    sa  += __shfl_xor_sync(0xffffffffu, sa, 1);
    smx += __shfl_xor_sync(0xffffffffu, smx, 1);
    if (h == 0) {
        float pre = g_sc[1]*sa + g_sc[2]*smx + g_sc[3];
        g_half[(size_t)(so*NB + n) * HW + p0 + p] = siluf(pre);
    }

    float zc = (h == 0) ? e : 0.f;
    #pragma unroll
    for (int k = 16; k >= 1; k >>= 1) zc += __shfl_xor_sync(0xffffffffu, zc, k);
    if ((t & 31) == 0) red[t >> 5] = zc;
    __syncthreads();    // also makes es[] visible block-wide
    if (t == 0) {
        float zs = 0.f;
        #pragma unroll
        for (int w = 0; w < 8; w++) zs += red[w];
        atomicAdd(&g_Z[so*NB + n], zs);
    }

    // fea[c] += sum_p V[c][p]*e[p]  (f32x2)
    #pragma unroll
    for (int i = 0; i < 4; i++) {
        int c = og + 16*i;
        ull fs2 = 0ULL;
        #pragma unroll
        for (int jp = 0; jp < 4; jp++)
            fs2 = fma2(*(const ull*)(Xs + c*TP + 2*pg + 32*jp),
                       *(const ull*)(es + 2*pg + 32*jp), fs2);
        float2 f = unpack2(fs2);
        float fs = f.x + f.y;
        #pragma unroll
        for (int k = 8; k >= 1; k >>= 1) fs += __shfl_xor_sync(0xffffffffu, fs, k);
        if (pg == 0) atomicAdd(&g_fea[(so*NB + n)*CCH + c], fs);
    }
}

// ---------------- gate: fea/Z -> convb -> LN -> sigmoid --------------------
__global__ void k_gate(const float* __restrict__ convb_w,
                       const float* __restrict__ ln_g, const float* __restrict__ ln_b) {
    int so = blockIdx.x, n = blockIdx.y, o = threadIdx.x;
    __shared__ float ff[64], tmp[64];
    int base = (so*NB + n) * CCH;
    float Z = g_Z[so*NB + n];
    ff[o] = g_fea[base + o] / Z;
    __syncthreads();
    float v = 0.f;
    for (int c = 0; c < 64; c++) v = fmaf(ff[c], convb_w[o*64 + c], v);
    float mu = blocksum64(v, tmp) * (1.f/64.f);
    float d = v - mu;
    float var = blocksum64(d*d, tmp) * (1.f/64.f);
    float gz = d * rsqrtf(var + EPSV) * ln_g[o] + ln_b[o];
    g_gate[base + o] = 1.f / (1.f + expf(-gz));
}

// ---------------- pass3: out = gate*half + me ------------------------------
__global__ void k_pass3(const float* __restrict__ xr, const float* __restrict__ xi,
                        float* __restrict__ out) {
    size_t g = (size_t)blockIdx.x * blockDim.x + threadIdx.x;  // float4 index
    int cl = (int)(g >> 14);          // s*512 + n*64 + c
    int p4 = (int)(g & 16383);
    int s = cl >> 9, n = (cl >> 6) & 7, c = cl & 63;
    float gate = g_gate[(s*NB + n)*CCH + c];
    float4 h4 = *(const float4*)(g_half + ((size_t)(s*NB + n) << 16) + (size_t)p4*4);
    const float* x = (s == 0 ? xr : xi);
    float4 m4 = *(const float4*)(x + (((size_t)n*64 + c) << 16) + (size_t)p4*4);
    float4 o4;
    o4.x = fmaf(gate, h4.x, m4.x);
    o4.y = fmaf(gate, h4.y, m4.y);
    o4.z = fmaf(gate, h4.z, m4.z);
    o4.w = fmaf(gate, h4.w, m4.w);
    *(float4*)(out + (g << 2)) = o4;
}

// ---------------- launch ---------------------------------------------------
extern "C" void kernel_launch(void* const* d_in, const int* in_sizes, int n_in,
                              void* d_out, int out_size) {
    const float* rgb    = (const float*)d_in[0];
    const float* ir     = (const float*)d_in[1];
    const float* conv_w = (const float*)d_in[2];
    const float* conv_b = (const float*)d_in[3];
    const float* key_w  = (const float*)d_in[4];
    const float* key_g  = (const float*)d_in[5];
    const float* key_b  = (const float*)d_in[6];
    const float* key_m  = (const float*)d_in[7];
    const float* key_v  = (const float*)d_in[8];
    const float* val_w  = (const float*)d_in[9];
    const float* val_g  = (const float*)d_in[10];
    const float* val_b  = (const float*)d_in[11];
    const float* val_m  = (const float*)d_in[12];
    const float* val_v  = (const float*)d_in[13];
    const float* convb_w= (const float*)d_in[14];
    const float* half_w = (const float*)d_in[15];
    const float* half_g = (const float*)d_in[16];
    const float* half_b = (const float*)d_in[17];
    const float* half_m = (const float*)d_in[18];
    const float* half_v = (const float*)d_in[19];
    const float* ln_g   = (const float*)d_in[20];
    const float* ln_b   = (const float*)d_in[21];
    float* out = (float*)d_out;

    const int SMEM1 = (8192 + 4160 + 64 + 8) * 4;
    const int SMEM2 = (8192 + 4160 + 64 + 64 + 64 + 128 + 8) * 4;
    cudaFuncSetAttribute(k_pass1, cudaFuncAttributeMaxDynamicSharedMemorySize, SMEM1);
    cudaFuncSetAttribute(k_pass2, cudaFuncAttributeMaxDynamicSharedMemorySize, SMEM2);

    k_init<<<1, 256>>>(key_w, key_g, key_b, key_m, key_v,
                       val_w, val_g, val_b, val_m, val_v,
                       half_w, half_g, half_b, half_m, half_v);
    dim3 gP(HW / TP, NB, 2);
    k_pass1<<<gP, 256, SMEM1>>>(rgb, ir, conv_w);
    k_mid<<<dim3(2, NB), 64>>>(conv_w, conv_b);
    k_pass2<<<gP, 256, SMEM2>>>(rgb, ir);
    k_gate<<<dim3(2, NB), 64>>>(convb_w, ln_g, ln_b);
    k_pass3<<<65536, 256>>>(rgb, ir, out);
}

// round 6
// speedup vs baseline: 1.5353x; 1.5353x over previous
#include <cuda_runtime.h>
#include <math.h>

#define EPSV 1e-5f
#define HW   65536
#define CCH  64
#define NB   8
#define TP   128

// ---------------- scratch (device globals; no runtime allocation) ----------
__device__ float    g_sumx[2*NB*CCH];
__device__ unsigned g_cmax[2*NB*CCH];
__device__ unsigned g_kmax[2*NB];
__device__ float    g_klog[2*NB*HW];     // 4 MB
__device__ float    g_fea [2*NB*CCH];
__device__ float    g_Z   [2*NB];
__device__ float    g_avg [2*NB*CCH];
__device__ float    g_msm [2*NB*CCH];
__device__ float    g_gate[2*NB*CCH];
__device__ float    g_half[2*NB*HW];     // 4 MB
__device__ float    g_keywf[CCH];
__device__ float    g_valwf[CCH*CCH];
__device__ float    g_valoff[CCH];
__device__ float    g_sc[4];             // keyoff, hw0, hw1, hoff

typedef unsigned long long ull;

// ---- f32x2 packed math (FFMA2 — only reachable via PTX) -------------------
__device__ __forceinline__ ull pack2(float a, float b) {
    ull r; asm("mov.b64 %0, {%1, %2};" : "=l"(r) : "f"(a), "f"(b)); return r;
}
__device__ __forceinline__ ull fma2(ull a, ull b, ull c) {
    ull d; asm("fma.rn.f32x2 %0, %1, %2, %3;" : "=l"(d) : "l"(a), "l"(b), "l"(c)); return d;
}
__device__ __forceinline__ float2 unpack2(ull v) {
    float2 f; asm("mov.b64 {%0, %1}, %2;" : "=f"(f.x), "=f"(f.y) : "l"(v)); return f;
}

// ordered-int encoding for float atomicMax
__device__ __forceinline__ unsigned ordf(float f) {
    unsigned u = __float_as_uint(f);
    return (u & 0x80000000u) ? ~u : (u | 0x80000000u);
}
__device__ __forceinline__ float deord(unsigned u) {
    u = (u & 0x80000000u) ? (u & 0x7fffffffu) : ~u;
    return __uint_as_float(u);
}
__device__ __forceinline__ float siluf(float z) {
    return __fdividef(z, 1.f + __expf(-z));
}

// ---------------- init: zero accumulators + fold BN into weights ----------
__global__ void k_init(const float* key_w, const float* key_g, const float* key_b,
                       const float* key_m, const float* key_v,
                       const float* val_w, const float* val_g, const float* val_b,
                       const float* val_m, const float* val_v,
                       const float* half_w, const float* half_g, const float* half_b,
                       const float* half_m, const float* half_v) {
    int t = threadIdx.x;
    for (int i = t; i < 2*NB*CCH; i += blockDim.x) { g_sumx[i] = 0.f; g_cmax[i] = 0u; g_fea[i] = 0.f; }
    for (int i = t; i < 2*NB; i += blockDim.x) { g_kmax[i] = 0u; g_Z[i] = 0.f; }
    if (t < CCH) {
        float ks = key_g[0] * rsqrtf(key_v[0] + EPSV);
        g_keywf[t] = key_w[t] * ks;
        float vs = val_g[t] * rsqrtf(val_v[t] + EPSV);
        g_valoff[t] = val_b[t] - val_m[t] * vs;
        for (int c = 0; c < CCH; c++) g_valwf[t*CCH + c] = val_w[t*CCH + c] * vs;
        if (t == 0) g_sc[0] = key_b[0] - key_m[0] * ks;
        if (t == 1) {
            float hs = half_g[0] * rsqrtf(half_v[0] + EPSV);
            g_sc[1] = half_w[0] * hs;
            g_sc[2] = half_w[1] * hs;
            g_sc[3] = half_b[0] - half_m[0] * hs;
        }
    }
}

// ---------------- pass1: conv_w GEMM -> channel max; x sums; key logits ----
// 256 threads, 64x128 tile. Thread (og=t>>4, pg=t&15) owns channels {og+16i}
// and pixel pairs {2pg+32jp, 2pg+32jp+1}.
__global__ void __launch_bounds__(256, 4)
k_pass1(const float* __restrict__ xr, const float* __restrict__ xi,
        const float* __restrict__ conv_w) {
    extern __shared__ float sm[];
    float* Xs  = sm;             // 64*128
    float* Ws  = sm + 8192;      // 64*65 (padded)
    float* kw  = Ws + 4160;      // 64
    float* red = kw + 64;        // 8
    int s = blockIdx.z, n = blockIdx.y;
    int p0 = blockIdx.x * TP;
    const float* x = (s == 0 ? xr : xi) + (size_t)n * CCH * HW + p0;
    int t = threadIdx.x;

    for (int i4 = t; i4 < 2048; i4 += 256) {
        int c = i4 >> 5, pq = i4 & 31;
        *(float4*)(Xs + c*TP + pq*4) = *(const float4*)(x + (size_t)c*HW + pq*4);
    }
    for (int i = t; i < 4096; i += 256) Ws[(i >> 6)*65 + (i & 63)] = conv_w[i];
    if (t < 64) kw[t] = g_keywf[t];
    __syncthreads();

    int og = t >> 4, pg = t & 15;
    const float* Wb = Ws + og*65;
    const float* Xb = Xs + 2*pg;

    ull acc2[4][4];
    #pragma unroll
    for (int i = 0; i < 4; i++)
        #pragma unroll
        for (int j = 0; j < 4; j++) acc2[i][j] = 0ULL;

    #pragma unroll 2
    for (int c = 0; c < 64; c++) {
        ull wv2[4], xv2[4];
        #pragma unroll
        for (int i = 0; i < 4; i++) { float w = Wb[i*(16*65) + c]; wv2[i] = pack2(w, w); }
        #pragma unroll
        for (int jp = 0; jp < 4; jp++) xv2[jp] = *(const ull*)(Xb + c*TP + 32*jp);
        #pragma unroll
        for (int i = 0; i < 4; i++)
            #pragma unroll
            for (int jp = 0; jp < 4; jp++) acc2[i][jp] = fma2(wv2[i], xv2[jp], acc2[i][jp]);
    }

    int base = (s*NB + n) * CCH;
    // per-channel max over pixels (bias added later)
    #pragma unroll
    for (int i = 0; i < 4; i++) {
        float m = -1e30f;
        #pragma unroll
        for (int jp = 0; jp < 4; jp++) {
            float2 f = unpack2(acc2[i][jp]);
            m = fmaxf(m, fmaxf(f.x, f.y));
        }
        #pragma unroll
        for (int k = 8; k >= 1; k >>= 1) m = fmaxf(m, __shfl_xor_sync(0xffffffffu, m, k));
        if (pg == 0) atomicMax(&g_cmax[base + og + 16*i], ordf(m));
    }
    // per-channel sums of x (exact mean path)
    #pragma unroll
    for (int i = 0; i < 4; i++) {
        int c = og + 16*i;
        float ssum = 0.f;
        #pragma unroll
        for (int jp = 0; jp < 4; jp++) {
            float2 v = *(const float2*)(Xs + c*TP + 2*pg + 32*jp);
            ssum += v.x + v.y;
        }
        #pragma unroll
        for (int k = 8; k >= 1; k >>= 1) ssum += __shfl_xor_sync(0xffffffffu, ssum, k);
        if (pg == 0) atomicAdd(&g_sumx[base + c], ssum);
    }
    // key logit: two threads per pixel, split channel halves
    int p = t >> 1, h = t & 1;
    float z = 0.f;
    #pragma unroll 8
    for (int c = 32*h; c < 32*h + 32; c++) z = fmaf(kw[c], Xs[c*TP + p], z);
    z += __shfl_xor_sync(0xffffffffu, z, 1);
    z += g_sc[0];
    float kl = siluf(z);
    if (h == 0) g_klog[(size_t)(s*NB + n) * HW + p0 + p] = kl;
    float km = (h == 0) ? kl : -1e30f;
    #pragma unroll
    for (int k = 16; k >= 1; k >>= 1) km = fmaxf(km, __shfl_xor_sync(0xffffffffu, km, k));
    if ((t & 31) == 0) red[t >> 5] = km;
    __syncthreads();
    if (t == 0) {
        float m = red[0];
        #pragma unroll
        for (int w = 1; w < 8; w++) m = fmaxf(m, red[w]);
        atomicMax(&g_kmax[s*NB + n], ordf(m));
    }
}

// ---------------- mid: channel softmaxes (avg from sums, max from cmax) ----
__device__ __forceinline__ float blockmax64(float v, float* tmp) {
    tmp[threadIdx.x] = v; __syncthreads();
    for (int k = 32; k >= 1; k >>= 1) {
        if (threadIdx.x < k) tmp[threadIdx.x] = fmaxf(tmp[threadIdx.x], tmp[threadIdx.x + k]);
        __syncthreads();
    }
    float r = tmp[0]; __syncthreads(); return r;
}
__device__ __forceinline__ float blocksum64(float v, float* tmp) {
    tmp[threadIdx.x] = v; __syncthreads();
    for (int k = 32; k >= 1; k >>= 1) {
        if (threadIdx.x < k) tmp[threadIdx.x] += tmp[threadIdx.x + k];
        __syncthreads();
    }
    float r = tmp[0]; __syncthreads(); return r;
}

__global__ void k_mid(const float* __restrict__ conv_w, const float* __restrict__ conv_b) {
    int s = blockIdx.x, n = blockIdx.y, o = threadIdx.x;
    __shared__ float sx[64], tmp[64];
    int base = (s*NB + n) * CCH;
    sx[o] = g_sumx[base + o] * (1.f / (float)HW);
    __syncthreads();
    float mean = conv_b[o];
    for (int c = 0; c < 64; c++) mean = fmaf(sx[c], conv_w[o*64 + c], mean);
    float mx = deord(g_cmax[base + o]) + conv_b[o];

    float m1 = blockmax64(mean, tmp);
    float e1 = expf(mean - m1);
    float s1 = blocksum64(e1, tmp);
    g_avg[base + o] = e1 / s1;

    float m2 = blockmax64(mx, tmp);
    float e2 = expf(mx - m2);
    float s2 = blocksum64(e2, tmp);
    g_msm[base + o] = e2 / s2;
}

// ---------------- pass2: val GEMM + fused fea/Z/half -----------------------
__global__ void __launch_bounds__(256, 4)
k_pass2(const float* __restrict__ xr, const float* __restrict__ xi) {
    extern __shared__ float sm[];
    float* Xs   = sm;            // 8192, reused as V after GEMM
    float* Ws   = sm + 8192;     // 4160
    float* voff = Ws + 4160;     // 64
    float* av   = voff + 64;     // 64
    float* mv   = av + 64;       // 64
    float* es   = mv + 64;       // 128
    float* red  = es + 128;      // 8
    int sx = blockIdx.z, n = blockIdx.y, so = 1 - sx;   // V of side sx feeds output side so
    int p0 = blockIdx.x * TP;
    int t = threadIdx.x;
    const float* x = (sx == 0 ? xr : xi) + (size_t)n * CCH * HW + p0;

    for (int i4 = t; i4 < 2048; i4 += 256) {
        int c = i4 >> 5, pq = i4 & 31;
        *(float4*)(Xs + c*TP + pq*4) = *(const float4*)(x + (size_t)c*HW + pq*4);
    }
    for (int i = t; i < 4096; i += 256) Ws[(i >> 6)*65 + (i & 63)] = g_valwf[i];
    if (t < 64) {
        voff[t] = g_valoff[t];
        int b2 = (so*NB + n) * CCH;
        av[t] = g_avg[b2 + t];
        mv[t] = g_msm[b2 + t];
    }
    __syncthreads();

    int og = t >> 4, pg = t & 15;
    const float* Wb = Ws + og*65;
    const float* Xb = Xs + 2*pg;

    ull acc2[4][4];
    #pragma unroll
    for (int i = 0; i < 4; i++)
        #pragma unroll
        for (int j = 0; j < 4; j++) acc2[i][j] = 0ULL;

    #pragma unroll 2
    for (int c = 0; c < 64; c++) {
        ull wv2[4], xv2[4];
        #pragma unroll
        for (int i = 0; i < 4; i++) { float w = Wb[i*(16*65) + c]; wv2[i] = pack2(w, w); }
        #pragma unroll
        for (int jp = 0; jp < 4; jp++) xv2[jp] = *(const ull*)(Xb + c*TP + 32*jp);
        #pragma unroll
        for (int i = 0; i < 4; i++)
            #pragma unroll
            for (int jp = 0; jp < 4; jp++) acc2[i][jp] = fma2(wv2[i], xv2[jp], acc2[i][jp]);
    }
    __syncthreads();   // done reading Xs; overwrite with V

    #pragma unroll
    for (int i = 0; i < 4; i++) {
        int c = og + 16*i;
        float off = voff[c];
        #pragma unroll
        for (int jp = 0; jp < 4; jp++) {
            float2 f = unpack2(acc2[i][jp]);
            f.x = siluf(f.x + off);
            f.y = siluf(f.y + off);
            *(float2*)(Xs + c*TP + 2*pg + 32*jp) = f;
        }
    }
    __syncthreads();

    // per-pixel: key weight e, half output (two threads per pixel)
    int p = t >> 1, h = t & 1;
    float kmaxv = deord(g_kmax[so*NB + n]);
    float kl = g_klog[(size_t)(so*NB + n) * HW + p0 + p];
    float e = __expf(kl - kmaxv);
    if (h == 0) es[p] = e;
    float sa = 0.f, smx = 0.f;
    #pragma unroll 8
    for (int c = 32*h; c < 32*h + 32; c++) {
        float vv = Xs[c*TP + p];
        sa  = fmaf(av[c], vv, sa);
        smx = fmaf(mv[c], vv, smx);
    }
    sa  += __shfl_xor_sync(0xffffffffu, sa, 1);
    smx += __shfl_xor_sync(0xffffffffu, smx, 1);
    if (h == 0) {
        float pre = g_sc[1]*sa + g_sc[2]*smx + g_sc[3];
        g_half[(size_t)(so*NB + n) * HW + p0 + p] = siluf(pre);
    }

    float zc = (h == 0) ? e : 0.f;
    #pragma unroll
    for (int k = 16; k >= 1; k >>= 1) zc += __shfl_xor_sync(0xffffffffu, zc, k);
    if ((t & 31) == 0) red[t >> 5] = zc;
    __syncthreads();    // also makes es[] visible block-wide
    if (t == 0) {
        float zs = 0.f;
        #pragma unroll
        for (int w = 0; w < 8; w++) zs += red[w];
        atomicAdd(&g_Z[so*NB + n], zs);
    }

    // fea[c] += sum_p V[c][p]*e[p]  (f32x2)
    #pragma unroll
    for (int i = 0; i < 4; i++) {
        int c = og + 16*i;
        ull fs2 = 0ULL;
        #pragma unroll
        for (int jp = 0; jp < 4; jp++)
            fs2 = fma2(*(const ull*)(Xs + c*TP + 2*pg + 32*jp),
                       *(const ull*)(es + 2*pg + 32*jp), fs2);
        float2 f = unpack2(fs2);
        float fs = f.x + f.y;
        #pragma unroll
        for (int k = 8; k >= 1; k >>= 1) fs += __shfl_xor_sync(0xffffffffu, fs, k);
        if (pg == 0) atomicAdd(&g_fea[(so*NB + n)*CCH + c], fs);
    }
}

// ---------------- gate: fea/Z -> convb -> LN -> sigmoid --------------------
__global__ void k_gate(const float* __restrict__ convb_w,
                       const float* __restrict__ ln_g, const float* __restrict__ ln_b) {
    int so = blockIdx.x, n = blockIdx.y, o = threadIdx.x;
    __shared__ float ff[64], tmp[64];
    int base = (so*NB + n) * CCH;
    float Z = g_Z[so*NB + n];
    ff[o] = g_fea[base + o] / Z;
    __syncthreads();
    float v = 0.f;
    for (int c = 0; c < 64; c++) v = fmaf(ff[c], convb_w[o*64 + c], v);
    float mu = blocksum64(v, tmp) * (1.f/64.f);
    float d = v - mu;
    float var = blocksum64(d*d, tmp) * (1.f/64.f);
    float gz = d * rsqrtf(var + EPSV) * ln_g[o] + ln_b[o];
    g_gate[base + o] = 1.f / (1.f + expf(-gz));
}

// ---------------- pass3: out = gate*half + me ------------------------------
__global__ void k_pass3(const float* __restrict__ xr, const float* __restrict__ xi,
                        float* __restrict__ out) {
    size_t g = (size_t)blockIdx.x * blockDim.x + threadIdx.x;  // float4 index
    int cl = (int)(g >> 14);          // s*512 + n*64 + c
    int p4 = (int)(g & 16383);
    int s = cl >> 9, n = (cl >> 6) & 7, c = cl & 63;
    float gate = g_gate[(s*NB + n)*CCH + c];
    float4 h4 = *(const float4*)(g_half + ((size_t)(s*NB + n) << 16) + (size_t)p4*4);
    const float* x = (s == 0 ? xr : xi);
    float4 m4 = *(const float4*)(x + (((size_t)n*64 + c) << 16) + (size_t)p4*4);
    float4 o4;
    o4.x = fmaf(gate, h4.x, m4.x);
    o4.y = fmaf(gate, h4.y, m4.y);
    o4.z = fmaf(gate, h4.z, m4.z);
    o4.w = fmaf(gate, h4.w, m4.w);
    *(float4*)(out + (g << 2)) = o4;
}

// ---------------- launch ---------------------------------------------------
extern "C" void kernel_launch(void* const* d_in, const int* in_sizes, int n_in,
                              void* d_out, int out_size) {
    const float* rgb    = (const float*)d_in[0];
    const float* ir     = (const float*)d_in[1];
    const float* conv_w = (const float*)d_in[2];
    const float* conv_b = (const float*)d_in[3];
    const float* key_w  = (const float*)d_in[4];
    const float* key_g  = (const float*)d_in[5];
    const float* key_b  = (const float*)d_in[6];
    const float* key_m  = (const float*)d_in[7];
    const float* key_v  = (const float*)d_in[8];
    const float* val_w  = (const float*)d_in[9];
    const float* val_g  = (const float*)d_in[10];
    const float* val_b  = (const float*)d_in[11];
    const float* val_m  = (const float*)d_in[12];
    const float* val_v  = (const float*)d_in[13];
    const float* convb_w= (const float*)d_in[14];
    const float* half_w = (const float*)d_in[15];
    const float* half_g = (const float*)d_in[16];
    const float* half_b = (const float*)d_in[17];
    const float* half_m = (const float*)d_in[18];
    const float* half_v = (const float*)d_in[19];
    const float* ln_g   = (const float*)d_in[20];
    const float* ln_b   = (const float*)d_in[21];
    float* out = (float*)d_out;

    const int SMEM1 = (8192 + 4160 + 64 + 8) * 4;
    const int SMEM2 = (8192 + 4160 + 64 + 64 + 64 + 128 + 8) * 4;
    cudaFuncSetAttribute(k_pass1, cudaFuncAttributeMaxDynamicSharedMemorySize, SMEM1);
    cudaFuncSetAttribute(k_pass2, cudaFuncAttributeMaxDynamicSharedMemorySize, SMEM2);

    k_init<<<1, 256>>>(key_w, key_g, key_b, key_m, key_v,
                       val_w, val_g, val_b, val_m, val_v,
                       half_w, half_g, half_b, half_m, half_v);
    dim3 gP(HW / TP, NB, 2);
    k_pass1<<<gP, 256, SMEM1>>>(rgb, ir, conv_w);
    k_mid<<<dim3(2, NB), 64>>>(conv_w, conv_b);
    k_pass2<<<gP, 256, SMEM2>>>(rgb, ir);
    k_gate<<<dim3(2, NB), 64>>>(convb_w, ln_g, ln_b);
    k_pass3<<<65536, 256>>>(rgb, ir, out);
}